// round 15
// baseline (speedup 1.0000x reference)
#include <cuda_runtime.h>
#include <cuda_fp16.h>
#include <math.h>
#include <cstdint>

#define BSZ 512
#define FD  512
#define HD  512
#define ED  8
#define OD  512
#define SK  4
#define WSTRIDE 262144L   // 512*512

// ---------------- scratch ----------------
__device__ float d_g [BSZ * ED];
__device__ float d_T [ED * BSZ * HD];          // fp32 T (layer 3); fp16 T aliases
__device__ float d_part[SK * BSZ * HD];

__device__ __align__(16) __half d_xh[BSZ * FD];
__device__ __align__(16) __half d_ah[BSZ * FD];
__device__ __align__(16) __half d_gh[BSZ * FD];   // gating L1 activations
__device__ __align__(16) __half d_g0h[HD * FD];
__device__ __align__(16) __half d_g1h[HD * HD];
__device__ __align__(16) __half d_w0h[ED * HD * FD];
__device__ __align__(16) __half d_w1h[ED * HD * HD];
__device__ __align__(16) __half d_w2h[ED * OD * HD];

__device__ __forceinline__ float elu1(float v) { return v > 0.f ? v : expm1f(v); }

__device__ __forceinline__ uint32_t smem_u32(const void* p) {
    uint32_t a;
    asm("{ .reg .u64 t; cvta.to.shared.u64 t, %1; cvt.u32.u64 %0, t; }" : "=r"(a) : "l"(p));
    return a;
}

#define CP16(dst, src) \
    asm volatile("cp.async.cg.shared.global [%0], [%1], 16;" :: "r"(dst), "l"(src))

#define LDSM4(r, addr) \
    asm volatile("ldmatrix.sync.aligned.m8n8.x4.shared.b16 {%0,%1,%2,%3}, [%4];" \
                 : "=r"((r)[0]), "=r"((r)[1]), "=r"((r)[2]), "=r"((r)[3]) : "r"(addr))

#define MMA16816F(d, a, b0, b1) \
    asm volatile("mma.sync.aligned.m16n8k16.row.col.f32.f16.f16.f32 " \
                 "{%0,%1,%2,%3},{%4,%5,%6,%7},{%8,%9},{%0,%1,%2,%3};" \
                 : "+f"((d)[0]), "+f"((d)[1]), "+f"((d)[2]), "+f"((d)[3]) \
                 : "r"((a)[0]), "r"((a)[1]), "r"((a)[2]), "r"((a)[3]), "r"(b0), "r"(b1))

__device__ __forceinline__ uint32_t pack_h2(float a, float b) {
    __half2 h = __floats2half2_rn(a, b);
    return *(uint32_t*)&h;
}

// ---------------- conversions ----------------
__device__ __forceinline__ void half_one(const float4* in, uint2* hi, int i) {
    float4 v = in[i];
    uint2 H;
    H.x = pack_h2(v.x, v.y); H.y = pack_h2(v.z, v.w);
    hi[i] = H;
}

// tiny front: x (256 blk), gw0 (256), gw1 (256) = 768 blocks
__global__ void __launch_bounds__(256)
conv_xg(const float4* __restrict__ x, uint2* __restrict__ xh,
        const float4* __restrict__ gw0, uint2* __restrict__ g0h,
        const float4* __restrict__ gw1, uint2* __restrict__ g1h)
{
    const int b = blockIdx.x;
    if (b < 256)       half_one(x,   xh,  b * 256 + threadIdx.x);
    else if (b < 512)  half_one(gw0, g0h, (b - 256) * 256 + threadIdx.x);
    else               half_one(gw1, g1h, (b - 512) * 256 + threadIdx.x);
}

// one expert-weight bank: 2048 blocks
__global__ void __launch_bounds__(256)
conv_one(const float4* __restrict__ in, uint2* __restrict__ outh)
{
    half_one(in, outh, blockIdx.x * 256 + threadIdx.x);
}

// ======== single-pass fp16 GEMM machinery (64x64 tile, BK=64, 2-stage) ========
#define LOAD_FRAGS_S(buf, ks)                                                       \
    do {                                                                            \
        const uint32_t achunk = (((uint32_t)((ks) << 1) + ahalf) ^ aswz) << 4;      \
        _Pragma("unroll")                                                           \
        for (int mi = 0; mi < 2; mi++) {                                            \
            const uint32_t roff = (uint32_t)((arow + mi * 16) * 128);               \
            LDSM4(af[buf][mi], Ah + roff + achunk);                                 \
        }                                                                           \
        _Pragma("unroll")                                                           \
        for (int np = 0; np < 2; np++) {                                            \
            const int brow = brow_base + np * 16;                                   \
            const uint32_t boff = (uint32_t)(brow * 128)                            \
                + ((((uint32_t)((ks) << 1) + bk) ^ (uint32_t)(brow & 7)) << 4);     \
            LDSM4(bf[buf][np], Bh + boff);                                          \
        }                                                                           \
    } while (0)

#define DO_MMAS_S(buf)                                                              \
    do {                                                                            \
        _Pragma("unroll")                                                           \
        for (int mi = 0; mi < 2; mi++)                                              \
            _Pragma("unroll")                                                       \
            for (int ni = 0; ni < 4; ni++)                                          \
                MMA16816F(acc[mi][ni], af[buf][mi], bf[buf][ni >> 1][(ni & 1) * 2], \
                          bf[buf][ni >> 1][(ni & 1) * 2 + 1]);                      \
    } while (0)

#define GEMM_SETUP()                                                                \
    extern __shared__ __align__(128) char smem[];                                   \
    const uint32_t sb = smem_u32(smem);                                             \
    const int tid = threadIdx.x;                                                    \
    const int wid = tid >> 5, lane = tid & 31;                                      \
    const int bm = blockIdx.y * 64, bn = blockIdx.x * 64;                           \
    const int lsub = tid >> 3;                                                      \
    const int lc16 = tid & 7;                                                       \
    const int warpM = wid & 1, warpN = wid >> 1;                                    \
    const int arow = warpM * 32 + (lane & 15);                                      \
    const uint32_t aswz = (uint32_t)(arow & 7);                                     \
    const uint32_t ahalf = (uint32_t)(lane >> 4);                                   \
    const int q = lane >> 3;                                                        \
    const int brow_base = warpN * 32 + ((q >> 1) << 3) + (lane & 7);                \
    const uint32_t bk = (uint32_t)(q & 1)

// ---------------- main expert GEMM ----------------
// out fp16 Ch (outHalf) or fp32 Cf, offset e*WSTRIDE.
__global__ void __launch_bounds__(128, 5)
tgemm(const __half* __restrict__ Ax, const __half* __restrict__ Bw,
      float* __restrict__ Cf, __half* __restrict__ Ch, int outHalf)
{
    GEMM_SETUP();
    const int e = blockIdx.z;
    const __half* Bp = Bw + (long)e * WSTRIDE;
    Cf += (long)e * WSTRIDE;
    Ch += (long)e * WSTRIDE;

    const __half* tp[2] = { Ax, Bp };
    const int toff[2] = { bm, bn };

    auto load_stage = [&](int kc, int buf) {
        const int k0 = kc << 6;
        const uint32_t base = sb + (uint32_t)buf * 16384u;
        #pragma unroll
        for (int t = 0; t < 2; t++) {
            const __half* P = tp[t];
            #pragma unroll
            for (int it = 0; it < 4; it++) {
                const int row = it * 16 + lsub;
                const uint32_t dst = base + (uint32_t)t * 8192u
                                   + (uint32_t)(row * 128 + ((lc16 ^ (row & 7)) << 4));
                CP16(dst, P + (long)(toff[t] + row) * 512 + k0 + lc16 * 8);
            }
        }
    };

    float acc[2][4][4] = {};
    uint32_t af[2][2][4], bf[2][2][4];

    load_stage(0, 0);
    asm volatile("cp.async.commit_group;" ::: "memory");

    for (int c = 0; c < 8; c++) {
        if (c + 1 < 8) {
            load_stage(c + 1, (c + 1) & 1);
            asm volatile("cp.async.commit_group;" ::: "memory");
            asm volatile("cp.async.wait_group 1;" ::: "memory");
        } else {
            asm volatile("cp.async.wait_group 0;" ::: "memory");
        }
        __syncthreads();

        const uint32_t S  = sb + (uint32_t)(c & 1) * 16384u;
        const uint32_t Ah = S, Bh = S + 8192u;

        LOAD_FRAGS_S(0, 0);
        #pragma unroll
        for (int ks = 0; ks < 4; ks++) {
            const int cur = ks & 1;
            if (ks < 3) LOAD_FRAGS_S(cur ^ 1, ks + 1);
            DO_MMAS_S(cur);
        }
        __syncthreads();
    }

    const int gr = lane >> 2, gc = (lane & 3) * 2;
    #pragma unroll
    for (int mi = 0; mi < 2; mi++) {
        const int row0 = bm + warpM * 32 + mi * 16 + gr;
        #pragma unroll
        for (int ni = 0; ni < 4; ni++) {
            const int col = bn + warpN * 32 + ni * 8 + gc;
            float v0 = acc[mi][ni][0], v1 = acc[mi][ni][1];
            float v2 = acc[mi][ni][2], v3 = acc[mi][ni][3];
            if (outHalf) {
                *(uint32_t*)&Ch[(long)row0 * 512 + col]       = pack_h2(v0, v1);
                *(uint32_t*)&Ch[(long)(row0 + 8) * 512 + col] = pack_h2(v2, v3);
            } else {
                *(float2*)&Cf[(long)row0 * 512 + col]       = make_float2(v0, v1);
                *(float2*)&Cf[(long)(row0 + 8) * 512 + col] = make_float2(v2, v3);
            }
        }
    }
}

// ---------------- split-K gating GEMM: grid (8,8,SK), z covers 2 chunks (K=128) ----------------
__global__ void __launch_bounds__(128, 5)
tgemm_sk(const __half* __restrict__ Ax, const __half* __restrict__ Bp,
         float* __restrict__ part)
{
    GEMM_SETUP();
    const int z = blockIdx.z;
    float* C = part + (long)z * BSZ * HD;

    const __half* tp[2] = { Ax, Bp };
    const int toff[2] = { bm, bn };

    auto load_stage = [&](int kc, int buf) {
        const int k0 = kc << 6;
        const uint32_t base = sb + (uint32_t)buf * 16384u;
        #pragma unroll
        for (int t = 0; t < 2; t++) {
            const __half* P = tp[t];
            #pragma unroll
            for (int it = 0; it < 4; it++) {
                const int row = it * 16 + lsub;
                const uint32_t dst = base + (uint32_t)t * 8192u
                                   + (uint32_t)(row * 128 + ((lc16 ^ (row & 7)) << 4));
                CP16(dst, P + (long)(toff[t] + row) * 512 + k0 + lc16 * 8);
            }
        }
    };

    float acc[2][4][4] = {};
    uint32_t af[2][2][4], bf[2][2][4];

    load_stage(z * 2, 0);
    asm volatile("cp.async.commit_group;" ::: "memory");
    load_stage(z * 2 + 1, 1);
    asm volatile("cp.async.commit_group;" ::: "memory");

    #pragma unroll
    for (int c = 0; c < 2; c++) {
        if (c == 0) asm volatile("cp.async.wait_group 1;" ::: "memory");
        else        asm volatile("cp.async.wait_group 0;" ::: "memory");
        __syncthreads();

        const uint32_t S  = sb + (uint32_t)(c & 1) * 16384u;
        const uint32_t Ah = S, Bh = S + 8192u;

        LOAD_FRAGS_S(0, 0);
        #pragma unroll
        for (int ks = 0; ks < 4; ks++) {
            const int cur = ks & 1;
            if (ks < 3) LOAD_FRAGS_S(cur ^ 1, ks + 1);
            DO_MMAS_S(cur);
        }
        __syncthreads();
    }

    const int gr = lane >> 2, gc = (lane & 3) * 2;
    #pragma unroll
    for (int mi = 0; mi < 2; mi++) {
        const int row0 = bm + warpM * 32 + mi * 16 + gr;
        #pragma unroll
        for (int ni = 0; ni < 4; ni++) {
            const int col = bn + warpN * 32 + ni * 8 + gc;
            *(float2*)&C[(long)row0 * 512 + col]       = make_float2(acc[mi][ni][0], acc[mi][ni][1]);
            *(float2*)&C[(long)(row0 + 8) * 512 + col] = make_float2(acc[mi][ni][2], acc[mi][ni][3]);
        }
    }
}

// ---------------- reduce partials + bias + elu -> fp16 (gating L1 output) ----------------
__global__ void __launch_bounds__(256)
reduce_l1(const float4* __restrict__ part, const float* __restrict__ bias,
          __half* __restrict__ gh)
{
    const int i4 = blockIdx.x * 256 + threadIdx.x;
    const int col = (i4 << 2) & 511;
    float4 s = part[i4];
    #pragma unroll
    for (int z = 1; z < SK; z++) {
        const float4 p = part[z * (BSZ * HD / 4) + i4];
        s.x += p.x; s.y += p.y; s.z += p.z; s.w += p.w;
    }
    s.x = elu1(s.x + bias[col]);     s.y = elu1(s.y + bias[col + 1]);
    s.z = elu1(s.z + bias[col + 2]); s.w = elu1(s.w + bias[col + 3]);
    uint2 H;
    H.x = pack_h2(s.x, s.y); H.y = pack_h2(s.z, s.w);
    ((uint2*)gh)[i4] = H;
}

// ---------------- fused: reduce gateL2 partials + bias + elu + logits + softmax ----------------
__global__ void __launch_bounds__(256)
reduce_softmax(const float* __restrict__ part, const float* __restrict__ gb1,
               const float* __restrict__ w2, const float* __restrict__ b2,
               float* __restrict__ g)
{
    __shared__ float s[512];
    __shared__ float lg[8];
    const int b = blockIdx.x, tid = threadIdx.x;
    for (int i = tid; i < 512; i += 256) {
        float v = part[(long)b * 512 + i];
        #pragma unroll
        for (int z = 1; z < SK; z++) v += part[(long)z * BSZ * HD + (long)b * 512 + i];
        s[i] = elu1(v + gb1[i]);
    }
    __syncthreads();

    const int w = tid >> 5, lane = tid & 31;
    float sum = 0.f;
    for (int i = lane; i < 512; i += 32) sum += s[i] * w2[(long)w * 512 + i];
    #pragma unroll
    for (int o = 16; o > 0; o >>= 1) sum += __shfl_xor_sync(0xffffffffu, sum, o);
    if (lane == 0) lg[w] = sum + b2[w];
    __syncthreads();

    if (tid == 0) {
        float mx = lg[0];
        #pragma unroll
        for (int i = 1; i < 8; i++) mx = fmaxf(mx, lg[i]);
        float ex[8], se = 0.f;
        #pragma unroll
        for (int i = 0; i < 8; i++) { ex[i] = expf(lg[i] - mx); se += ex[i]; }
        float inv = 1.f / se;
        #pragma unroll
        for (int i = 0; i < 8; i++) g[(long)b * 8 + i] = ex[i] * inv;
    }
}

// ---------------- blends ----------------
__global__ void __launch_bounds__(256)
blend_half(const uint2* __restrict__ Th, const float* __restrict__ g,
           const float4* __restrict__ beta4, __half* __restrict__ Oh)
{
    const int i4 = blockIdx.x * 256 + threadIdx.x;
    const int base = i4 << 2;
    const int b = base >> 9, h4 = (base & 511) >> 2;
    float4 sum = make_float4(0.f, 0.f, 0.f, 0.f);
    #pragma unroll
    for (int e = 0; e < 8; e++) {
        const float ge = g[b * 8 + e];
        const uint2 U = Th[(e << 16) + i4];
        const float2 f0 = __half22float2(*(const __half2*)&U.x);
        const float2 f1 = __half22float2(*(const __half2*)&U.y);
        const float4 be = beta4[(e << 7) + h4];
        sum.x += ge * (f0.x + be.x); sum.y += ge * (f0.y + be.y);
        sum.z += ge * (f1.x + be.z); sum.w += ge * (f1.y + be.w);
    }
    uint2 H;
    H.x = pack_h2(elu1(sum.x), elu1(sum.y));
    H.y = pack_h2(elu1(sum.z), elu1(sum.w));
    ((uint2*)Oh)[i4] = H;
}

__global__ void __launch_bounds__(256)
blend_final(const float4* __restrict__ T4, const float* __restrict__ g,
            const float4* __restrict__ beta4, float* __restrict__ out)
{
    const int i4 = blockIdx.x * 256 + threadIdx.x;
    const int base = i4 << 2;
    const int b = base >> 9, h4 = (base & 511) >> 2;
    float4 sum = make_float4(0.f, 0.f, 0.f, 0.f);
    #pragma unroll
    for (int e = 0; e < 8; e++) {
        const float ge = g[b * 8 + e];
        const float4 t = T4[(e << 16) + i4];
        const float4 be = beta4[(e << 7) + h4];
        sum.x += ge * (t.x + be.x); sum.y += ge * (t.y + be.y);
        sum.z += ge * (t.z + be.z); sum.w += ge * (t.w + be.w);
    }
    ((float4*)out)[i4] = sum;
}

// ---------------- launch ----------------
extern "C" void kernel_launch(void* const* d_in, const int* in_sizes, int n_in,
                              void* d_out, int out_size)
{
    const float* x      = (const float*)d_in[0];
    const float* gw0    = (const float*)d_in[1];
    const float* gb0    = (const float*)d_in[2];
    const float* gw1    = (const float*)d_in[3];
    const float* gb1    = (const float*)d_in[4];
    const float* gw2    = (const float*)d_in[5];
    const float* gb2    = (const float*)d_in[6];
    const float* alpha0 = (const float*)d_in[7];
    const float* beta0  = (const float*)d_in[8];
    const float* alpha1 = (const float*)d_in[9];
    const float* beta1  = (const float*)d_in[10];
    const float* alpha2 = (const float*)d_in[11];
    const float* beta2  = (const float*)d_in[12];
    float* out = (float*)d_out;

    float *gp, *T, *part;
    cudaGetSymbolAddress((void**)&gp, d_g);
    cudaGetSymbolAddress((void**)&T,  d_T);
    cudaGetSymbolAddress((void**)&part, d_part);
    __half* Th = (__half*)T;

    __half *xh, *ah, *gh, *g0h, *g1h, *w0h, *w1h, *w2h;
    cudaGetSymbolAddress((void**)&xh,  d_xh);  cudaGetSymbolAddress((void**)&ah,  d_ah);
    cudaGetSymbolAddress((void**)&gh,  d_gh);
    cudaGetSymbolAddress((void**)&g0h, d_g0h); cudaGetSymbolAddress((void**)&g1h, d_g1h);
    cudaGetSymbolAddress((void**)&w0h, d_w0h); cudaGetSymbolAddress((void**)&w1h, d_w1h);
    cudaGetSymbolAddress((void**)&w2h, d_w2h);

    const int SMEM_SZ = 2 * 16384;   // 32KB/CTA -> 5 CTAs/SM
    cudaFuncSetAttribute(tgemm,    cudaFuncAttributeMaxDynamicSharedMemorySize, SMEM_SZ);
    cudaFuncSetAttribute(tgemm_sk, cudaFuncAttributeMaxDynamicSharedMemorySize, SMEM_SZ);

    dim3 g8(8, 8, 8), gSK(8, 8, SK);
    const int BLEND_B = (BSZ * HD / 4) / 256;   // 256 blocks

    // ONE auxiliary stream (verified-safe resource profile).
    cudaStream_t s2;
    cudaStreamCreate(&s2);
    cudaEvent_t eStart, eXG, eGate, eW1, eW2;
    cudaEventCreateWithFlags(&eStart, cudaEventDisableTiming);
    cudaEventCreateWithFlags(&eXG,    cudaEventDisableTiming);
    cudaEventCreateWithFlags(&eGate,  cudaEventDisableTiming);
    cudaEventCreateWithFlags(&eW1,    cudaEventDisableTiming);
    cudaEventCreateWithFlags(&eW2,    cudaEventDisableTiming);

    cudaEventRecord(eStart, 0);
    cudaStreamWaitEvent(s2, eStart, 0);

    // main: tiny front conversion (x, gw0, gw1) -- unblocks the gate chain fast
    conv_xg<<<768, 256>>>((const float4*)x, (uint2*)xh,
                          (const float4*)gw0, (uint2*)g0h,
                          (const float4*)gw1, (uint2*)g1h);
    cudaEventRecord(eXG, 0);

    // s2: gate chain FIRST, then w1/w2 conversions fill the tail
    cudaStreamWaitEvent(s2, eXG, 0);
    tgemm_sk<<<gSK, 128, SMEM_SZ, s2>>>(xh, g0h, part);
    reduce_l1<<<BLEND_B, 256, 0, s2>>>((const float4*)part, gb0, gh);
    tgemm_sk<<<gSK, 128, SMEM_SZ, s2>>>(gh, g1h, part);
    reduce_softmax<<<BSZ, 256, 0, s2>>>(part, gb1, gw2, gb2, gp);
    cudaEventRecord(eGate, s2);
    conv_one<<<2048, 256, 0, s2>>>((const float4*)alpha1, (uint2*)w1h);
    cudaEventRecord(eW1, s2);
    conv_one<<<2048, 256, 0, s2>>>((const float4*)alpha2, (uint2*)w2h);
    cudaEventRecord(eW2, s2);

    // main: w0 conversion + expert layer-1 GEMM (concurrent with gate chain)
    conv_one<<<2048, 256>>>((const float4*)alpha0, (uint2*)w0h);
    tgemm<<<g8, 128, SMEM_SZ>>>(xh, w0h, T, Th, 1);
    cudaStreamWaitEvent(0, eGate, 0);
    blend_half<<<BLEND_B, 256>>>((const uint2*)Th, gp, (const float4*)beta0, ah);

    // expert layer 2 (needs w1)
    cudaStreamWaitEvent(0, eW1, 0);
    tgemm<<<g8, 128, SMEM_SZ>>>(ah, w1h, T, Th, 1);
    blend_half<<<BLEND_B, 256>>>((const uint2*)Th, gp, (const float4*)beta1, ah);

    // expert layer 3 (needs w2; T fp32) + final blend
    cudaStreamWaitEvent(0, eW2, 0);
    tgemm<<<g8, 128, SMEM_SZ>>>(ah, w2h, T, Th, 0);
    blend_final<<<BLEND_B, 256>>>((const float4*)T, gp, (const float4*)beta2, out);
}

// round 16
// speedup vs baseline: 1.1941x; 1.1941x over previous
#include <cuda_runtime.h>
#include <cuda_fp16.h>
#include <math.h>
#include <cstdint>

#define BSZ 512
#define FD  512
#define HD  512
#define ED  8
#define OD  512
#define SK  4
#define WSTRIDE 262144L   // 512*512

// ---------------- scratch ----------------
__device__ float d_g [BSZ * ED];
__device__ float d_T [ED * BSZ * HD];          // fp32 T (layer 3); fp16 T aliases
__device__ float d_part[SK * BSZ * HD];

__device__ __align__(16) __half d_xh[BSZ * FD];
__device__ __align__(16) __half d_ah[BSZ * FD];
__device__ __align__(16) __half d_gh[BSZ * FD];
__device__ __align__(16) __half d_g0h[HD * FD];
__device__ __align__(16) __half d_g1h[HD * HD];
__device__ __align__(16) __half d_w0h[ED * HD * FD];
__device__ __align__(16) __half d_w1h[ED * HD * HD];
__device__ __align__(16) __half d_w2h[ED * OD * HD];

__device__ __forceinline__ float elu1(float v) { return v > 0.f ? v : expm1f(v); }

__device__ __forceinline__ uint32_t smem_u32(const void* p) {
    uint32_t a;
    asm("{ .reg .u64 t; cvta.to.shared.u64 t, %1; cvt.u32.u64 %0, t; }" : "=r"(a) : "l"(p));
    return a;
}

#define CP16(dst, src) \
    asm volatile("cp.async.cg.shared.global [%0], [%1], 16;" :: "r"(dst), "l"(src))

#define LDSM4(r, addr) \
    asm volatile("ldmatrix.sync.aligned.m8n8.x4.shared.b16 {%0,%1,%2,%3}, [%4];" \
                 : "=r"((r)[0]), "=r"((r)[1]), "=r"((r)[2]), "=r"((r)[3]) : "r"(addr))

#define MMA16816F(d, a, b0, b1) \
    asm volatile("mma.sync.aligned.m16n8k16.row.col.f32.f16.f16.f32 " \
                 "{%0,%1,%2,%3},{%4,%5,%6,%7},{%8,%9},{%0,%1,%2,%3};" \
                 : "+f"((d)[0]), "+f"((d)[1]), "+f"((d)[2]), "+f"((d)[3]) \
                 : "r"((a)[0]), "r"((a)[1]), "r"((a)[2]), "r"((a)[3]), "r"(b0), "r"(b1))

__device__ __forceinline__ uint32_t pack_h2(float a, float b) {
    __half2 h = __floats2half2_rn(a, b);
    return *(uint32_t*)&h;
}

// ---------------- conversions ----------------
__device__ __forceinline__ void half_one(const float4* in, uint2* hi, int i) {
    float4 v = in[i];
    uint2 H;
    H.x = pack_h2(v.x, v.y); H.y = pack_h2(v.z, v.w);
    hi[i] = H;
}

// front: x (256), gw0 (256), gw1 (256), w0 (2048) = 2816 blocks
__global__ void __launch_bounds__(256)
conv_front(const float4* __restrict__ x, uint2* __restrict__ xh,
           const float4* __restrict__ gw0, uint2* __restrict__ g0h,
           const float4* __restrict__ gw1, uint2* __restrict__ g1h,
           const float4* __restrict__ a0, uint2* __restrict__ w0h)
{
    const int b = blockIdx.x;
    if (b < 256)       half_one(x,   xh,  b * 256 + threadIdx.x);
    else if (b < 512)  half_one(gw0, g0h, (b - 256) * 256 + threadIdx.x);
    else if (b < 768)  half_one(gw1, g1h, (b - 512) * 256 + threadIdx.x);
    else               half_one(a0,  w0h, (b - 768) * 256 + threadIdx.x);
}

// one expert-weight bank: 2048 blocks
__global__ void __launch_bounds__(256)
conv_one(const float4* __restrict__ in, uint2* __restrict__ outh)
{
    half_one(in, outh, blockIdx.x * 256 + threadIdx.x);
}

// ======== single-pass fp16 GEMM machinery (64x64 tile, BK=64) ========
#define LOAD_FRAGS_S(buf, ks)                                                       \
    do {                                                                            \
        const uint32_t achunk = (((uint32_t)((ks) << 1) + ahalf) ^ aswz) << 4;      \
        _Pragma("unroll")                                                           \
        for (int mi = 0; mi < 2; mi++) {                                            \
            const uint32_t roff = (uint32_t)((arow + mi * 16) * 128);               \
            LDSM4(af[buf][mi], Ah + roff + achunk);                                 \
        }                                                                           \
        _Pragma("unroll")                                                           \
        for (int np = 0; np < 2; np++) {                                            \
            const int brow = brow_base + np * 16;                                   \
            const uint32_t boff = (uint32_t)(brow * 128)                            \
                + ((((uint32_t)((ks) << 1) + bk) ^ (uint32_t)(brow & 7)) << 4);     \
            LDSM4(bf[buf][np], Bh + boff);                                          \
        }                                                                           \
    } while (0)

#define DO_MMAS_S(buf)                                                              \
    do {                                                                            \
        _Pragma("unroll")                                                           \
        for (int mi = 0; mi < 2; mi++)                                              \
            _Pragma("unroll")                                                       \
            for (int ni = 0; ni < 4; ni++)                                          \
                MMA16816F(acc[mi][ni], af[buf][mi], bf[buf][ni >> 1][(ni & 1) * 2], \
                          bf[buf][ni >> 1][(ni & 1) * 2 + 1]);                      \
    } while (0)

#define GEMM_SETUP()                                                                \
    extern __shared__ __align__(128) char smem[];                                   \
    const uint32_t sb = smem_u32(smem);                                             \
    const int tid = threadIdx.x;                                                    \
    const int wid = tid >> 5, lane = tid & 31;                                      \
    const int bm = blockIdx.y * 64, bn = blockIdx.x * 64;                           \
    const int lsub = tid >> 3;                                                      \
    const int lc16 = tid & 7;                                                       \
    const int warpM = wid & 1, warpN = wid >> 1;                                    \
    const int arow = warpM * 32 + (lane & 15);                                      \
    const uint32_t aswz = (uint32_t)(arow & 7);                                     \
    const uint32_t ahalf = (uint32_t)(lane >> 4);                                   \
    const int q = lane >> 3;                                                        \
    const int brow_base = warpN * 32 + ((q >> 1) << 3) + (lane & 7);                \
    const uint32_t bk = (uint32_t)(q & 1)

// ---------------- main expert GEMM: 3-stage cp.async pipeline ----------------
__global__ void __launch_bounds__(128, 4)
tgemm(const __half* __restrict__ Ax, const __half* __restrict__ Bw,
      float* __restrict__ Cf, __half* __restrict__ Ch, int outHalf)
{
    GEMM_SETUP();
    const int e = blockIdx.z;
    const __half* Bp = Bw + (long)e * WSTRIDE;
    Cf += (long)e * WSTRIDE;
    Ch += (long)e * WSTRIDE;

    const __half* tp[2] = { Ax, Bp };
    const int toff[2] = { bm, bn };

    auto load_stage = [&](int kc, int buf) {
        const int k0 = kc << 6;
        const uint32_t base = sb + (uint32_t)buf * 16384u;
        #pragma unroll
        for (int t = 0; t < 2; t++) {
            const __half* P = tp[t];
            #pragma unroll
            for (int it = 0; it < 4; it++) {
                const int row = it * 16 + lsub;
                const uint32_t dst = base + (uint32_t)t * 8192u
                                   + (uint32_t)(row * 128 + ((lc16 ^ (row & 7)) << 4));
                CP16(dst, P + (long)(toff[t] + row) * 512 + k0 + lc16 * 8);
            }
        }
    };

    float acc[2][4][4] = {};
    uint32_t af[2][2][4], bf[2][2][4];

    load_stage(0, 0);
    asm volatile("cp.async.commit_group;" ::: "memory");
    load_stage(1, 1);
    asm volatile("cp.async.commit_group;" ::: "memory");

    for (int c = 0; c < 8; c++) {
        if (c + 2 < 8) {
            load_stage(c + 2, (c + 2) % 3);
            asm volatile("cp.async.commit_group;" ::: "memory");
            asm volatile("cp.async.wait_group 2;" ::: "memory");
        } else if (c == 6) {
            asm volatile("cp.async.wait_group 1;" ::: "memory");
        } else if (c == 7) {
            asm volatile("cp.async.wait_group 0;" ::: "memory");
        }
        __syncthreads();

        const uint32_t S  = sb + (uint32_t)(c % 3) * 16384u;
        const uint32_t Ah = S, Bh = S + 8192u;

        LOAD_FRAGS_S(0, 0);
        #pragma unroll
        for (int ks = 0; ks < 4; ks++) {
            const int cur = ks & 1;
            if (ks < 3) LOAD_FRAGS_S(cur ^ 1, ks + 1);
            DO_MMAS_S(cur);
        }
        __syncthreads();
    }

    const int gr = lane >> 2, gc = (lane & 3) * 2;
    #pragma unroll
    for (int mi = 0; mi < 2; mi++) {
        const int row0 = bm + warpM * 32 + mi * 16 + gr;
        #pragma unroll
        for (int ni = 0; ni < 4; ni++) {
            const int col = bn + warpN * 32 + ni * 8 + gc;
            float v0 = acc[mi][ni][0], v1 = acc[mi][ni][1];
            float v2 = acc[mi][ni][2], v3 = acc[mi][ni][3];
            if (outHalf) {
                *(uint32_t*)&Ch[(long)row0 * 512 + col]       = pack_h2(v0, v1);
                *(uint32_t*)&Ch[(long)(row0 + 8) * 512 + col] = pack_h2(v2, v3);
            } else {
                *(float2*)&Cf[(long)row0 * 512 + col]       = make_float2(v0, v1);
                *(float2*)&Cf[(long)(row0 + 8) * 512 + col] = make_float2(v2, v3);
            }
        }
    }
}

// ---------------- split-K gating GEMM: grid (8,8,SK), z covers 2 chunks (K=128) ----------------
__global__ void __launch_bounds__(128, 5)
tgemm_sk(const __half* __restrict__ Ax, const __half* __restrict__ Bp,
         float* __restrict__ part)
{
    GEMM_SETUP();
    const int z = blockIdx.z;
    float* C = part + (long)z * BSZ * HD;

    const __half* tp[2] = { Ax, Bp };
    const int toff[2] = { bm, bn };

    auto load_stage = [&](int kc, int buf) {
        const int k0 = kc << 6;
        const uint32_t base = sb + (uint32_t)buf * 16384u;
        #pragma unroll
        for (int t = 0; t < 2; t++) {
            const __half* P = tp[t];
            #pragma unroll
            for (int it = 0; it < 4; it++) {
                const int row = it * 16 + lsub;
                const uint32_t dst = base + (uint32_t)t * 8192u
                                   + (uint32_t)(row * 128 + ((lc16 ^ (row & 7)) << 4));
                CP16(dst, P + (long)(toff[t] + row) * 512 + k0 + lc16 * 8);
            }
        }
    };

    float acc[2][4][4] = {};
    uint32_t af[2][2][4], bf[2][2][4];

    load_stage(z * 2, 0);
    asm volatile("cp.async.commit_group;" ::: "memory");
    load_stage(z * 2 + 1, 1);
    asm volatile("cp.async.commit_group;" ::: "memory");

    #pragma unroll
    for (int c = 0; c < 2; c++) {
        if (c == 0) asm volatile("cp.async.wait_group 1;" ::: "memory");
        else        asm volatile("cp.async.wait_group 0;" ::: "memory");
        __syncthreads();

        const uint32_t S  = sb + (uint32_t)(c & 1) * 16384u;
        const uint32_t Ah = S, Bh = S + 8192u;

        LOAD_FRAGS_S(0, 0);
        #pragma unroll
        for (int ks = 0; ks < 4; ks++) {
            const int cur = ks & 1;
            if (ks < 3) LOAD_FRAGS_S(cur ^ 1, ks + 1);
            DO_MMAS_S(cur);
        }
        __syncthreads();
    }

    const int gr = lane >> 2, gc = (lane & 3) * 2;
    #pragma unroll
    for (int mi = 0; mi < 2; mi++) {
        const int row0 = bm + warpM * 32 + mi * 16 + gr;
        #pragma unroll
        for (int ni = 0; ni < 4; ni++) {
            const int col = bn + warpN * 32 + ni * 8 + gc;
            *(float2*)&C[(long)row0 * 512 + col]       = make_float2(acc[mi][ni][0], acc[mi][ni][1]);
            *(float2*)&C[(long)(row0 + 8) * 512 + col] = make_float2(acc[mi][ni][2], acc[mi][ni][3]);
        }
    }
}

// ---------------- reduce partials + bias + elu -> fp16 (gating L1 output) ----------------
__global__ void __launch_bounds__(256)
reduce_l1(const float4* __restrict__ part, const float* __restrict__ bias,
          __half* __restrict__ gh)
{
    const int i4 = blockIdx.x * 256 + threadIdx.x;
    const int col = (i4 << 2) & 511;
    float4 s = part[i4];
    #pragma unroll
    for (int z = 1; z < SK; z++) {
        const float4 p = part[z * (BSZ * HD / 4) + i4];
        s.x += p.x; s.y += p.y; s.z += p.z; s.w += p.w;
    }
    s.x = elu1(s.x + bias[col]);     s.y = elu1(s.y + bias[col + 1]);
    s.z = elu1(s.z + bias[col + 2]); s.w = elu1(s.w + bias[col + 3]);
    uint2 H;
    H.x = pack_h2(s.x, s.y); H.y = pack_h2(s.z, s.w);
    ((uint2*)gh)[i4] = H;
}

// ---------------- fused: reduce gateL2 partials + bias + elu + logits + softmax ----------------
__global__ void __launch_bounds__(256)
reduce_softmax(const float* __restrict__ part, const float* __restrict__ gb1,
               const float* __restrict__ w2, const float* __restrict__ b2,
               float* __restrict__ g)
{
    __shared__ float s[512];
    __shared__ float lg[8];
    const int b = blockIdx.x, tid = threadIdx.x;
    for (int i = tid; i < 512; i += 256) {
        float v = part[(long)b * 512 + i];
        #pragma unroll
        for (int z = 1; z < SK; z++) v += part[(long)z * BSZ * HD + (long)b * 512 + i];
        s[i] = elu1(v + gb1[i]);
    }
    __syncthreads();

    const int w = tid >> 5, lane = tid & 31;
    float sum = 0.f;
    for (int i = lane; i < 512; i += 32) sum += s[i] * w2[(long)w * 512 + i];
    #pragma unroll
    for (int o = 16; o > 0; o >>= 1) sum += __shfl_xor_sync(0xffffffffu, sum, o);
    if (lane == 0) lg[w] = sum + b2[w];
    __syncthreads();

    if (tid == 0) {
        float mx = lg[0];
        #pragma unroll
        for (int i = 1; i < 8; i++) mx = fmaxf(mx, lg[i]);
        float ex[8], se = 0.f;
        #pragma unroll
        for (int i = 0; i < 8; i++) { ex[i] = expf(lg[i] - mx); se += ex[i]; }
        float inv = 1.f / se;
        #pragma unroll
        for (int i = 0; i < 8; i++) g[(long)b * 8 + i] = ex[i] * inv;
    }
}

// ---------------- blends ----------------
__global__ void __launch_bounds__(256)
blend_half(const uint2* __restrict__ Th, const float* __restrict__ g,
           const float4* __restrict__ beta4, __half* __restrict__ Oh)
{
    const int i4 = blockIdx.x * 256 + threadIdx.x;
    const int base = i4 << 2;
    const int b = base >> 9, h4 = (base & 511) >> 2;
    float4 sum = make_float4(0.f, 0.f, 0.f, 0.f);
    #pragma unroll
    for (int e = 0; e < 8; e++) {
        const float ge = g[b * 8 + e];
        const uint2 U = Th[(e << 16) + i4];
        const float2 f0 = __half22float2(*(const __half2*)&U.x);
        const float2 f1 = __half22float2(*(const __half2*)&U.y);
        const float4 be = beta4[(e << 7) + h4];
        sum.x += ge * (f0.x + be.x); sum.y += ge * (f0.y + be.y);
        sum.z += ge * (f1.x + be.z); sum.w += ge * (f1.y + be.w);
    }
    uint2 H;
    H.x = pack_h2(elu1(sum.x), elu1(sum.y));
    H.y = pack_h2(elu1(sum.z), elu1(sum.w));
    ((uint2*)Oh)[i4] = H;
}

__global__ void __launch_bounds__(256)
blend_final(const float4* __restrict__ T4, const float* __restrict__ g,
            const float4* __restrict__ beta4, float* __restrict__ out)
{
    const int i4 = blockIdx.x * 256 + threadIdx.x;
    const int base = i4 << 2;
    const int b = base >> 9, h4 = (base & 511) >> 2;
    float4 sum = make_float4(0.f, 0.f, 0.f, 0.f);
    #pragma unroll
    for (int e = 0; e < 8; e++) {
        const float ge = g[b * 8 + e];
        const float4 t = T4[(e << 16) + i4];
        const float4 be = beta4[(e << 7) + h4];
        sum.x += ge * (t.x + be.x); sum.y += ge * (t.y + be.y);
        sum.z += ge * (t.z + be.z); sum.w += ge * (t.w + be.w);
    }
    ((float4*)out)[i4] = sum;
}

// ---------------- launch ----------------
extern "C" void kernel_launch(void* const* d_in, const int* in_sizes, int n_in,
                              void* d_out, int out_size)
{
    const float* x      = (const float*)d_in[0];
    const float* gw0    = (const float*)d_in[1];
    const float* gb0    = (const float*)d_in[2];
    const float* gw1    = (const float*)d_in[3];
    const float* gb1    = (const float*)d_in[4];
    const float* gw2    = (const float*)d_in[5];
    const float* gb2    = (const float*)d_in[6];
    const float* alpha0 = (const float*)d_in[7];
    const float* beta0  = (const float*)d_in[8];
    const float* alpha1 = (const float*)d_in[9];
    const float* beta1  = (const float*)d_in[10];
    const float* alpha2 = (const float*)d_in[11];
    const float* beta2  = (const float*)d_in[12];
    float* out = (float*)d_out;

    float *gp, *T, *part;
    cudaGetSymbolAddress((void**)&gp, d_g);
    cudaGetSymbolAddress((void**)&T,  d_T);
    cudaGetSymbolAddress((void**)&part, d_part);
    __half* Th = (__half*)T;

    __half *xh, *ah, *gh, *g0h, *g1h, *w0h, *w1h, *w2h;
    cudaGetSymbolAddress((void**)&xh,  d_xh);  cudaGetSymbolAddress((void**)&ah,  d_ah);
    cudaGetSymbolAddress((void**)&gh,  d_gh);
    cudaGetSymbolAddress((void**)&g0h, d_g0h); cudaGetSymbolAddress((void**)&g1h, d_g1h);
    cudaGetSymbolAddress((void**)&w0h, d_w0h); cudaGetSymbolAddress((void**)&w1h, d_w1h);
    cudaGetSymbolAddress((void**)&w2h, d_w2h);

    const int SMEM_G = 3 * 16384;   // 48KB -> occupancy 4 (grid-limited anyway)
    const int SMEM_S = 2 * 16384;
    cudaFuncSetAttribute(tgemm,    cudaFuncAttributeMaxDynamicSharedMemorySize, SMEM_G);
    cudaFuncSetAttribute(tgemm_sk, cudaFuncAttributeMaxDynamicSharedMemorySize, SMEM_S);

    dim3 g8(8, 8, 8), gSK(8, 8, SK);
    const int BLEND_B = (BSZ * HD / 4) / 256;

    // ONE auxiliary stream.
    cudaStream_t s2;
    cudaStreamCreate(&s2);
    cudaEvent_t eFront, eGate, eW1, eW2;
    cudaEventCreateWithFlags(&eFront, cudaEventDisableTiming);
    cudaEventCreateWithFlags(&eGate,  cudaEventDisableTiming);
    cudaEventCreateWithFlags(&eW1,    cudaEventDisableTiming);
    cudaEventCreateWithFlags(&eW2,    cudaEventDisableTiming);

    // main: front conversions (x, gw0, gw1, w0)
    conv_front<<<2816, 256>>>((const float4*)x, (uint2*)xh,
                              (const float4*)gw0, (uint2*)g0h,
                              (const float4*)gw1, (uint2*)g1h,
                              (const float4*)alpha0, (uint2*)w0h);
    cudaEventRecord(eFront, 0);

    // s2: gate chain first (hidden under L1 GEMM), then w1, then w2
    cudaStreamWaitEvent(s2, eFront, 0);
    tgemm_sk<<<gSK, 128, SMEM_S, s2>>>(xh, g0h, part);
    reduce_l1<<<BLEND_B, 256, 0, s2>>>((const float4*)part, gb0, gh);
    tgemm_sk<<<gSK, 128, SMEM_S, s2>>>(gh, g1h, part);
    reduce_softmax<<<BSZ, 256, 0, s2>>>(part, gb1, gw2, gb2, gp);
    cudaEventRecord(eGate, s2);
    conv_one<<<2048, 256, 0, s2>>>((const float4*)alpha1, (uint2*)w1h);
    cudaEventRecord(eW1, s2);
    conv_one<<<2048, 256, 0, s2>>>((const float4*)alpha2, (uint2*)w2h);
    cudaEventRecord(eW2, s2);

    // main: expert layer-1 GEMM (3-stage), then join gate before blend
    tgemm<<<g8, 128, SMEM_G>>>(xh, w0h, T, Th, 1);
    cudaStreamWaitEvent(0, eGate, 0);
    blend_half<<<BLEND_B, 256>>>((const uint2*)Th, gp, (const float4*)beta0, ah);

    // expert layer 2 (needs w1)
    cudaStreamWaitEvent(0, eW1, 0);
    tgemm<<<g8, 128, SMEM_G>>>(ah, w1h, T, Th, 1);
    blend_half<<<BLEND_B, 256>>>((const uint2*)Th, gp, (const float4*)beta1, ah);

    // expert layer 3 (needs w2; T fp32) + final blend
    cudaStreamWaitEvent(0, eW2, 0);
    tgemm<<<g8, 128, SMEM_G>>>(ah, w2h, T, Th, 0);
    blend_final<<<BLEND_B, 256>>>((const float4*)T, gp, (const float4*)beta2, out);
}

// round 17
// speedup vs baseline: 1.1993x; 1.0043x over previous
#include <cuda_runtime.h>
#include <cuda_fp16.h>
#include <math.h>
#include <cstdint>

#define BSZ 512
#define FD  512
#define HD  512
#define ED  8
#define OD  512
#define SK  4
#define WSTRIDE 262144L   // 512*512

// ---------------- scratch ----------------
__device__ float d_g [BSZ * ED];
__device__ float d_T [ED * BSZ * HD];          // fp32 T (layer 3); fp16 T aliases
__device__ float d_part[SK * BSZ * HD];

__device__ __align__(16) __half d_xh[BSZ * FD];
__device__ __align__(16) __half d_ah[BSZ * FD];
__device__ __align__(16) __half d_gh[BSZ * FD];
__device__ __align__(16) __half d_g0h[HD * FD];
__device__ __align__(16) __half d_g1h[HD * HD];
__device__ __align__(16) __half d_w0h[ED * HD * FD];
__device__ __align__(16) __half d_w1h[ED * HD * HD];
__device__ __align__(16) __half d_w2h[ED * OD * HD];

__device__ __forceinline__ float elu1(float v) { return v > 0.f ? v : expm1f(v); }

__device__ __forceinline__ uint32_t smem_u32(const void* p) {
    uint32_t a;
    asm("{ .reg .u64 t; cvta.to.shared.u64 t, %1; cvt.u32.u64 %0, t; }" : "=r"(a) : "l"(p));
    return a;
}

#define CP16(dst, src) \
    asm volatile("cp.async.cg.shared.global [%0], [%1], 16;" :: "r"(dst), "l"(src))

#define LDSM4(r, addr) \
    asm volatile("ldmatrix.sync.aligned.m8n8.x4.shared.b16 {%0,%1,%2,%3}, [%4];" \
                 : "=r"((r)[0]), "=r"((r)[1]), "=r"((r)[2]), "=r"((r)[3]) : "r"(addr))

#define MMA16816F(d, a, b0, b1) \
    asm volatile("mma.sync.aligned.m16n8k16.row.col.f32.f16.f16.f32 " \
                 "{%0,%1,%2,%3},{%4,%5,%6,%7},{%8,%9},{%0,%1,%2,%3};" \
                 : "+f"((d)[0]), "+f"((d)[1]), "+f"((d)[2]), "+f"((d)[3]) \
                 : "r"((a)[0]), "r"((a)[1]), "r"((a)[2]), "r"((a)[3]), "r"(b0), "r"(b1))

__device__ __forceinline__ uint32_t pack_h2(float a, float b) {
    __half2 h = __floats2half2_rn(a, b);
    return *(uint32_t*)&h;
}

// ---------------- conversions ----------------
__device__ __forceinline__ void half_one(const float4* in, uint2* hi, int i) {
    float4 v = in[i];
    uint2 H;
    H.x = pack_h2(v.x, v.y); H.y = pack_h2(v.z, v.w);
    hi[i] = H;
}

// main front: x (256 blk) + w0 (2048 blk) = 2304 blocks
__global__ void __launch_bounds__(256)
conv_xw0(const float4* __restrict__ x, uint2* __restrict__ xh,
         const float4* __restrict__ a0, uint2* __restrict__ w0h)
{
    const int b = blockIdx.x;
    if (b < 256) half_one(x,  xh,  b * 256 + threadIdx.x);
    else         half_one(a0, w0h, (b - 256) * 256 + threadIdx.x);
}

// s2 head: gw0 (256) + gw1 (256) = 512 blocks
__global__ void __launch_bounds__(256)
conv_g01(const float4* __restrict__ gw0, uint2* __restrict__ g0h,
         const float4* __restrict__ gw1, uint2* __restrict__ g1h)
{
    const int b = blockIdx.x;
    if (b < 256) half_one(gw0, g0h, b * 256 + threadIdx.x);
    else         half_one(gw1, g1h, (b - 256) * 256 + threadIdx.x);
}

// one expert-weight bank: 2048 blocks
__global__ void __launch_bounds__(256)
conv_one(const float4* __restrict__ in, uint2* __restrict__ outh)
{
    half_one(in, outh, blockIdx.x * 256 + threadIdx.x);
}

// ======== single-pass fp16 GEMM machinery (64x64 tile, BK=64) ========
#define LOAD_FRAGS_S(buf, ks)                                                       \
    do {                                                                            \
        const uint32_t achunk = (((uint32_t)((ks) << 1) + ahalf) ^ aswz) << 4;      \
        _Pragma("unroll")                                                           \
        for (int mi = 0; mi < 2; mi++) {                                            \
            const uint32_t roff = (uint32_t)((arow + mi * 16) * 128);               \
            LDSM4(af[buf][mi], Ah + roff + achunk);                                 \
        }                                                                           \
        _Pragma("unroll")                                                           \
        for (int np = 0; np < 2; np++) {                                            \
            const int brow = brow_base + np * 16;                                   \
            const uint32_t boff = (uint32_t)(brow * 128)                            \
                + ((((uint32_t)((ks) << 1) + bk) ^ (uint32_t)(brow & 7)) << 4);     \
            LDSM4(bf[buf][np], Bh + boff);                                          \
        }                                                                           \
    } while (0)

#define DO_MMAS_S(buf)                                                              \
    do {                                                                            \
        _Pragma("unroll")                                                           \
        for (int mi = 0; mi < 2; mi++)                                              \
            _Pragma("unroll")                                                       \
            for (int ni = 0; ni < 4; ni++)                                          \
                MMA16816F(acc[mi][ni], af[buf][mi], bf[buf][ni >> 1][(ni & 1) * 2], \
                          bf[buf][ni >> 1][(ni & 1) * 2 + 1]);                      \
    } while (0)

#define GEMM_SETUP()                                                                \
    extern __shared__ __align__(128) char smem[];                                   \
    const uint32_t sb = smem_u32(smem);                                             \
    const int tid = threadIdx.x;                                                    \
    const int wid = tid >> 5, lane = tid & 31;                                      \
    const int bm = blockIdx.y * 64, bn = blockIdx.x * 64;                           \
    const int lsub = tid >> 3;                                                      \
    const int lc16 = tid & 7;                                                       \
    const int warpM = wid & 1, warpN = wid >> 1;                                    \
    const int arow = warpM * 32 + (lane & 15);                                      \
    const uint32_t aswz = (uint32_t)(arow & 7);                                     \
    const uint32_t ahalf = (uint32_t)(lane >> 4);                                   \
    const int q = lane >> 3;                                                        \
    const int brow_base = warpN * 32 + ((q >> 1) << 3) + (lane & 7);                \
    const uint32_t bk = (uint32_t)(q & 1)

// ---------------- main expert GEMM: 3-stage cp.async pipeline ----------------
__global__ void __launch_bounds__(128, 4)
tgemm(const __half* __restrict__ Ax, const __half* __restrict__ Bw,
      float* __restrict__ Cf, __half* __restrict__ Ch, int outHalf)
{
    GEMM_SETUP();
    const int e = blockIdx.z;
    const __half* Bp = Bw + (long)e * WSTRIDE;
    Cf += (long)e * WSTRIDE;
    Ch += (long)e * WSTRIDE;

    const __half* tp[2] = { Ax, Bp };
    const int toff[2] = { bm, bn };

    auto load_stage = [&](int kc, int buf) {
        const int k0 = kc << 6;
        const uint32_t base = sb + (uint32_t)buf * 16384u;
        #pragma unroll
        for (int t = 0; t < 2; t++) {
            const __half* P = tp[t];
            #pragma unroll
            for (int it = 0; it < 4; it++) {
                const int row = it * 16 + lsub;
                const uint32_t dst = base + (uint32_t)t * 8192u
                                   + (uint32_t)(row * 128 + ((lc16 ^ (row & 7)) << 4));
                CP16(dst, P + (long)(toff[t] + row) * 512 + k0 + lc16 * 8);
            }
        }
    };

    float acc[2][4][4] = {};
    uint32_t af[2][2][4], bf[2][2][4];

    load_stage(0, 0);
    asm volatile("cp.async.commit_group;" ::: "memory");
    load_stage(1, 1);
    asm volatile("cp.async.commit_group;" ::: "memory");

    for (int c = 0; c < 8; c++) {
        if (c + 2 < 8) {
            load_stage(c + 2, (c + 2) % 3);
            asm volatile("cp.async.commit_group;" ::: "memory");
            asm volatile("cp.async.wait_group 2;" ::: "memory");
        } else if (c == 6) {
            asm volatile("cp.async.wait_group 1;" ::: "memory");
        } else if (c == 7) {
            asm volatile("cp.async.wait_group 0;" ::: "memory");
        }
        __syncthreads();

        const uint32_t S  = sb + (uint32_t)(c % 3) * 16384u;
        const uint32_t Ah = S, Bh = S + 8192u;

        LOAD_FRAGS_S(0, 0);
        #pragma unroll
        for (int ks = 0; ks < 4; ks++) {
            const int cur = ks & 1;
            if (ks < 3) LOAD_FRAGS_S(cur ^ 1, ks + 1);
            DO_MMAS_S(cur);
        }
        __syncthreads();
    }

    const int gr = lane >> 2, gc = (lane & 3) * 2;
    #pragma unroll
    for (int mi = 0; mi < 2; mi++) {
        const int row0 = bm + warpM * 32 + mi * 16 + gr;
        #pragma unroll
        for (int ni = 0; ni < 4; ni++) {
            const int col = bn + warpN * 32 + ni * 8 + gc;
            float v0 = acc[mi][ni][0], v1 = acc[mi][ni][1];
            float v2 = acc[mi][ni][2], v3 = acc[mi][ni][3];
            if (outHalf) {
                *(uint32_t*)&Ch[(long)row0 * 512 + col]       = pack_h2(v0, v1);
                *(uint32_t*)&Ch[(long)(row0 + 8) * 512 + col] = pack_h2(v2, v3);
            } else {
                *(float2*)&Cf[(long)row0 * 512 + col]       = make_float2(v0, v1);
                *(float2*)&Cf[(long)(row0 + 8) * 512 + col] = make_float2(v2, v3);
            }
        }
    }
}

// ---------------- split-K gating GEMM: grid (8,8,SK), z covers 2 chunks (K=128) ----------------
__global__ void __launch_bounds__(128, 5)
tgemm_sk(const __half* __restrict__ Ax, const __half* __restrict__ Bp,
         float* __restrict__ part)
{
    GEMM_SETUP();
    const int z = blockIdx.z;
    float* C = part + (long)z * BSZ * HD;

    const __half* tp[2] = { Ax, Bp };
    const int toff[2] = { bm, bn };

    auto load_stage = [&](int kc, int buf) {
        const int k0 = kc << 6;
        const uint32_t base = sb + (uint32_t)buf * 16384u;
        #pragma unroll
        for (int t = 0; t < 2; t++) {
            const __half* P = tp[t];
            #pragma unroll
            for (int it = 0; it < 4; it++) {
                const int row = it * 16 + lsub;
                const uint32_t dst = base + (uint32_t)t * 8192u
                                   + (uint32_t)(row * 128 + ((lc16 ^ (row & 7)) << 4));
                CP16(dst, P + (long)(toff[t] + row) * 512 + k0 + lc16 * 8);
            }
        }
    };

    float acc[2][4][4] = {};
    uint32_t af[2][2][4], bf[2][2][4];

    load_stage(z * 2, 0);
    asm volatile("cp.async.commit_group;" ::: "memory");
    load_stage(z * 2 + 1, 1);
    asm volatile("cp.async.commit_group;" ::: "memory");

    #pragma unroll
    for (int c = 0; c < 2; c++) {
        if (c == 0) asm volatile("cp.async.wait_group 1;" ::: "memory");
        else        asm volatile("cp.async.wait_group 0;" ::: "memory");
        __syncthreads();

        const uint32_t S  = sb + (uint32_t)(c & 1) * 16384u;
        const uint32_t Ah = S, Bh = S + 8192u;

        LOAD_FRAGS_S(0, 0);
        #pragma unroll
        for (int ks = 0; ks < 4; ks++) {
            const int cur = ks & 1;
            if (ks < 3) LOAD_FRAGS_S(cur ^ 1, ks + 1);
            DO_MMAS_S(cur);
        }
        __syncthreads();
    }

    const int gr = lane >> 2, gc = (lane & 3) * 2;
    #pragma unroll
    for (int mi = 0; mi < 2; mi++) {
        const int row0 = bm + warpM * 32 + mi * 16 + gr;
        #pragma unroll
        for (int ni = 0; ni < 4; ni++) {
            const int col = bn + warpN * 32 + ni * 8 + gc;
            *(float2*)&C[(long)row0 * 512 + col]       = make_float2(acc[mi][ni][0], acc[mi][ni][1]);
            *(float2*)&C[(long)(row0 + 8) * 512 + col] = make_float2(acc[mi][ni][2], acc[mi][ni][3]);
        }
    }
}

// ---------------- reduce partials + bias + elu -> fp16 (gating L1 output) ----------------
__global__ void __launch_bounds__(256)
reduce_l1(const float4* __restrict__ part, const float* __restrict__ bias,
          __half* __restrict__ gh)
{
    const int i4 = blockIdx.x * 256 + threadIdx.x;
    const int col = (i4 << 2) & 511;
    float4 s = part[i4];
    #pragma unroll
    for (int z = 1; z < SK; z++) {
        const float4 p = part[z * (BSZ * HD / 4) + i4];
        s.x += p.x; s.y += p.y; s.z += p.z; s.w += p.w;
    }
    s.x = elu1(s.x + bias[col]);     s.y = elu1(s.y + bias[col + 1]);
    s.z = elu1(s.z + bias[col + 2]); s.w = elu1(s.w + bias[col + 3]);
    uint2 H;
    H.x = pack_h2(s.x, s.y); H.y = pack_h2(s.z, s.w);
    ((uint2*)gh)[i4] = H;
}

// ---------------- fused: reduce gateL2 partials + bias + elu + logits + softmax ----------------
__global__ void __launch_bounds__(256)
reduce_softmax(const float* __restrict__ part, const float* __restrict__ gb1,
               const float* __restrict__ w2, const float* __restrict__ b2,
               float* __restrict__ g)
{
    __shared__ float s[512];
    __shared__ float lg[8];
    const int b = blockIdx.x, tid = threadIdx.x;
    for (int i = tid; i < 512; i += 256) {
        float v = part[(long)b * 512 + i];
        #pragma unroll
        for (int z = 1; z < SK; z++) v += part[(long)z * BSZ * HD + (long)b * 512 + i];
        s[i] = elu1(v + gb1[i]);
    }
    __syncthreads();

    const int w = tid >> 5, lane = tid & 31;
    float sum = 0.f;
    for (int i = lane; i < 512; i += 32) sum += s[i] * w2[(long)w * 512 + i];
    #pragma unroll
    for (int o = 16; o > 0; o >>= 1) sum += __shfl_xor_sync(0xffffffffu, sum, o);
    if (lane == 0) lg[w] = sum + b2[w];
    __syncthreads();

    if (tid == 0) {
        float mx = lg[0];
        #pragma unroll
        for (int i = 1; i < 8; i++) mx = fmaxf(mx, lg[i]);
        float ex[8], se = 0.f;
        #pragma unroll
        for (int i = 0; i < 8; i++) { ex[i] = expf(lg[i] - mx); se += ex[i]; }
        float inv = 1.f / se;
        #pragma unroll
        for (int i = 0; i < 8; i++) g[(long)b * 8 + i] = ex[i] * inv;
    }
}

// ---------------- blends (grid 512 x 128 threads) ----------------
__global__ void __launch_bounds__(128)
blend_half(const uint2* __restrict__ Th, const float* __restrict__ g,
           const float4* __restrict__ beta4, __half* __restrict__ Oh)
{
    const int i4 = blockIdx.x * 128 + threadIdx.x;
    const int base = i4 << 2;
    const int b = base >> 9, h4 = (base & 511) >> 2;
    float4 sum = make_float4(0.f, 0.f, 0.f, 0.f);
    #pragma unroll
    for (int e = 0; e < 8; e++) {
        const float ge = g[b * 8 + e];
        const uint2 U = Th[(e << 16) + i4];
        const float2 f0 = __half22float2(*(const __half2*)&U.x);
        const float2 f1 = __half22float2(*(const __half2*)&U.y);
        const float4 be = beta4[(e << 7) + h4];
        sum.x += ge * (f0.x + be.x); sum.y += ge * (f0.y + be.y);
        sum.z += ge * (f1.x + be.z); sum.w += ge * (f1.y + be.w);
    }
    uint2 H;
    H.x = pack_h2(elu1(sum.x), elu1(sum.y));
    H.y = pack_h2(elu1(sum.z), elu1(sum.w));
    ((uint2*)Oh)[i4] = H;
}

__global__ void __launch_bounds__(128)
blend_final(const float4* __restrict__ T4, const float* __restrict__ g,
            const float4* __restrict__ beta4, float* __restrict__ out)
{
    const int i4 = blockIdx.x * 128 + threadIdx.x;
    const int base = i4 << 2;
    const int b = base >> 9, h4 = (base & 511) >> 2;
    float4 sum = make_float4(0.f, 0.f, 0.f, 0.f);
    #pragma unroll
    for (int e = 0; e < 8; e++) {
        const float ge = g[b * 8 + e];
        const float4 t = T4[(e << 16) + i4];
        const float4 be = beta4[(e << 7) + h4];
        sum.x += ge * (t.x + be.x); sum.y += ge * (t.y + be.y);
        sum.z += ge * (t.z + be.z); sum.w += ge * (t.w + be.w);
    }
    ((float4*)out)[i4] = sum;
}

// ---------------- launch ----------------
extern "C" void kernel_launch(void* const* d_in, const int* in_sizes, int n_in,
                              void* d_out, int out_size)
{
    const float* x      = (const float*)d_in[0];
    const float* gw0    = (const float*)d_in[1];
    const float* gb0    = (const float*)d_in[2];
    const float* gw1    = (const float*)d_in[3];
    const float* gb1    = (const float*)d_in[4];
    const float* gw2    = (const float*)d_in[5];
    const float* gb2    = (const float*)d_in[6];
    const float* alpha0 = (const float*)d_in[7];
    const float* beta0  = (const float*)d_in[8];
    const float* alpha1 = (const float*)d_in[9];
    const float* beta1  = (const float*)d_in[10];
    const float* alpha2 = (const float*)d_in[11];
    const float* beta2  = (const float*)d_in[12];
    float* out = (float*)d_out;

    float *gp, *T, *part;
    cudaGetSymbolAddress((void**)&gp, d_g);
    cudaGetSymbolAddress((void**)&T,  d_T);
    cudaGetSymbolAddress((void**)&part, d_part);
    __half* Th = (__half*)T;

    __half *xh, *ah, *gh, *g0h, *g1h, *w0h, *w1h, *w2h;
    cudaGetSymbolAddress((void**)&xh,  d_xh);  cudaGetSymbolAddress((void**)&ah,  d_ah);
    cudaGetSymbolAddress((void**)&gh,  d_gh);
    cudaGetSymbolAddress((void**)&g0h, d_g0h); cudaGetSymbolAddress((void**)&g1h, d_g1h);
    cudaGetSymbolAddress((void**)&w0h, d_w0h); cudaGetSymbolAddress((void**)&w1h, d_w1h);
    cudaGetSymbolAddress((void**)&w2h, d_w2h);

    const int SMEM_G = 3 * 16384;   // 48KB -> occ 4 (single wave for grid 512)
    const int SMEM_S = 2 * 16384;
    cudaFuncSetAttribute(tgemm,    cudaFuncAttributeMaxDynamicSharedMemorySize, SMEM_G);
    cudaFuncSetAttribute(tgemm_sk, cudaFuncAttributeMaxDynamicSharedMemorySize, SMEM_S);

    dim3 g8(8, 8, 8), gSK(8, 8, SK);
    const int BLEND_B = (BSZ * HD / 4) / 128;   // 512 blocks x 128 thr
    const int RED_B   = (BSZ * HD / 4) / 256;   // 256 blocks x 256 thr

    // ONE auxiliary stream.
    cudaStream_t s2;
    cudaStreamCreate(&s2);
    cudaEvent_t eFront, eGate, eW1, eW2;
    cudaEventCreateWithFlags(&eFront, cudaEventDisableTiming);
    cudaEventCreateWithFlags(&eGate,  cudaEventDisableTiming);
    cudaEventCreateWithFlags(&eW1,    cudaEventDisableTiming);
    cudaEventCreateWithFlags(&eW2,    cudaEventDisableTiming);

    // s2 head: gating-weight conversions run concurrent with main front
    conv_g01<<<512, 256, 0, s2>>>((const float4*)gw0, (uint2*)g0h,
                                  (const float4*)gw1, (uint2*)g1h);

    // main: front conversions (x + w0 only)
    conv_xw0<<<2304, 256>>>((const float4*)x, (uint2*)xh,
                            (const float4*)alpha0, (uint2*)w0h);
    cudaEventRecord(eFront, 0);

    // s2: gate chain (hidden under L1 GEMM), then w1, then w2
    cudaStreamWaitEvent(s2, eFront, 0);
    tgemm_sk<<<gSK, 128, SMEM_S, s2>>>(xh, g0h, part);
    reduce_l1<<<RED_B, 256, 0, s2>>>((const float4*)part, gb0, gh);
    tgemm_sk<<<gSK, 128, SMEM_S, s2>>>(gh, g1h, part);
    reduce_softmax<<<BSZ, 256, 0, s2>>>(part, gb1, gw2, gb2, gp);
    cudaEventRecord(eGate, s2);
    conv_one<<<2048, 256, 0, s2>>>((const float4*)alpha1, (uint2*)w1h);
    cudaEventRecord(eW1, s2);
    conv_one<<<2048, 256, 0, s2>>>((const float4*)alpha2, (uint2*)w2h);
    cudaEventRecord(eW2, s2);

    // main: expert layer-1 GEMM (3-stage), then join gate before blend
    tgemm<<<g8, 128, SMEM_G>>>(xh, w0h, T, Th, 1);
    cudaStreamWaitEvent(0, eGate, 0);
    blend_half<<<BLEND_B, 128>>>((const uint2*)Th, gp, (const float4*)beta0, ah);

    // expert layer 2 (needs w1)
    cudaStreamWaitEvent(0, eW1, 0);
    tgemm<<<g8, 128, SMEM_G>>>(ah, w1h, T, Th, 1);
    blend_half<<<BLEND_B, 128>>>((const uint2*)Th, gp, (const float4*)beta1, ah);

    // expert layer 3 (needs w2; T fp32) + final blend
    cudaStreamWaitEvent(0, eW2, 0);
    tgemm<<<g8, 128, SMEM_G>>>(ah, w2h, T, Th, 0);
    blend_final<<<BLEND_B, 128>>>((const float4*)T, gp, (const float4*)beta2, out);
}